// round 3
// baseline (speedup 1.0000x reference)
#include <cuda_runtime.h>
#include <cstdint>

// Problem constants (match reference_code)
#define N_NEURONS 100000
#define AVG_CONN  500
#define N_STEPS   10
#define DECAY     0.95f
#define NV4       (N_NEURONS / 4)   // 25000, N_NEURONS % 4 == 0

// Persistent state in device globals (no allocation allowed).
// Zero-initialized at module load; kernels below restore the zero state of the
// post buffers as they consume them, so graph replays are idempotent.
__device__ __align__(16) float g_pot[N_NEURONS];
__device__ __align__(16) float g_th[N_NEURONS];
__device__ __align__(16) float g_post[2][N_NEURONS];

// Scatter one fired neuron's 500 outgoing edges (rare path).
__device__ __forceinline__ void scatter_edges(int i,
                                              const float* __restrict__ weights,
                                              const int*   __restrict__ conn,
                                              float* __restrict__ pb)
{
    const float4* __restrict__ w4 = reinterpret_cast<const float4*>(weights + (size_t)i * AVG_CONN);
    const int4*   __restrict__ c4 = reinterpret_cast<const int4*>(conn + (size_t)i * AVG_CONN);
    #pragma unroll 4
    for (int k = 0; k < AVG_CONN / 4; k++) {
        float4 w = w4[k];
        int4   c = c4[k];
        atomicAdd(&pb[c.x], w.x);
        atomicAdd(&pb[c.y], w.y);
        atomicAdd(&pb[c.z], w.z);
        atomicAdd(&pb[c.w], w.w);
    }
}

// One fused kernel per simulation step, 4 neurons per thread (float4 path):
//   1. (t>0) apply previous step's accumulated post: pot += sign * post_prev; zero post_prev
//   2. pot = pot*DECAY + noise[t] (+ external_input at t==0, reading pot0/th0)
//   3. fired test, threshold update
//   4. per fired lane: scatter 500 weighted edges into post_cur via atomicAdd
// Double buffering (prev != cur) makes step 1 and step 4 race-free within one launch.
__global__ void __launch_bounds__(256)
step_kernel(const float* __restrict__ noise_t,
            const float* __restrict__ ext,
            const float* __restrict__ pot0,
            const float* __restrict__ th0,
            const float* __restrict__ inhib,
            const float* __restrict__ weights,
            const int*   __restrict__ conn,
            int prev_buf, int cur_buf, int is_first)
{
    int v = blockIdx.x * blockDim.x + threadIdx.x;
    if (v >= NV4) return;
    int i0 = v * 4;

    float4 pot, th;
    float4 nz = reinterpret_cast<const float4*>(noise_t)[v];

    if (is_first) {
        pot = reinterpret_cast<const float4*>(pot0)[v];
        th  = reinterpret_cast<const float4*>(th0)[v];
        float4 ex = reinterpret_cast<const float4*>(ext)[v];
        pot.x = pot.x * DECAY + nz.x + ex.x;
        pot.y = pot.y * DECAY + nz.y + ex.y;
        pot.z = pot.z * DECAY + nz.z + ex.z;
        pot.w = pot.w * DECAY + nz.w + ex.w;
    } else {
        pot = reinterpret_cast<const float4*>(g_pot)[v];
        th  = reinterpret_cast<const float4*>(g_th)[v];
        float4* pprev = reinterpret_cast<float4*>(g_post[prev_buf]);
        float4 p  = pprev[v];
        pprev[v] = make_float4(0.f, 0.f, 0.f, 0.f);   // consume + reset for reuse
        float4 ih = reinterpret_cast<const float4*>(inhib)[v];
        pot.x = fmaf(1.0f - 2.0f * ih.x, p.x, pot.x) * DECAY + nz.x;
        pot.y = fmaf(1.0f - 2.0f * ih.y, p.y, pot.y) * DECAY + nz.y;
        pot.z = fmaf(1.0f - 2.0f * ih.z, p.z, pot.z) * DECAY + nz.z;
        pot.w = fmaf(1.0f - 2.0f * ih.w, p.w, pot.w) * DECAY + nz.w;
    }

    bool f0 = pot.x >= th.x;
    bool f1 = pot.y >= th.y;
    bool f2 = pot.z >= th.z;
    bool f3 = pot.w >= th.w;

    th.x = fminf(fmaxf(th.x + (f0 ? 0.4f : -0.1f), 1.0f), 100.0f);
    th.y = fminf(fmaxf(th.y + (f1 ? 0.4f : -0.1f), 1.0f), 100.0f);
    th.z = fminf(fmaxf(th.z + (f2 ? 0.4f : -0.1f), 1.0f), 100.0f);
    th.w = fminf(fmaxf(th.w + (f3 ? 0.4f : -0.1f), 1.0f), 100.0f);

    reinterpret_cast<float4*>(g_pot)[v] = pot;
    reinterpret_cast<float4*>(g_th)[v]  = th;

    if (f0 | f1 | f2 | f3) {
        float* pb = g_post[cur_buf];
        if (f0) scatter_edges(i0 + 0, weights, conn, pb);
        if (f1) scatter_edges(i0 + 1, weights, conn, pb);
        if (f2) scatter_edges(i0 + 2, weights, conn, pb);
        if (f3) scatter_edges(i0 + 3, weights, conn, pb);
    }
}

// Final kernel: apply the last step's post and emit the output potentials.
// Also zeroes the buffer so the module state is clean for the next graph replay.
__global__ void __launch_bounds__(256)
final_kernel(const float* __restrict__ inhib,
             float* __restrict__ out,
             int buf)
{
    int v = blockIdx.x * blockDim.x + threadIdx.x;
    if (v >= NV4) return;
    float4* pbuf = reinterpret_cast<float4*>(g_post[buf]);
    float4 p  = pbuf[v];
    pbuf[v] = make_float4(0.f, 0.f, 0.f, 0.f);
    float4 ih = reinterpret_cast<const float4*>(inhib)[v];
    float4 pot = reinterpret_cast<const float4*>(g_pot)[v];
    float4 o;
    o.x = fmaf(1.0f - 2.0f * ih.x, p.x, pot.x);
    o.y = fmaf(1.0f - 2.0f * ih.y, p.y, pot.y);
    o.z = fmaf(1.0f - 2.0f * ih.z, p.z, pot.z);
    o.w = fmaf(1.0f - 2.0f * ih.w, p.w, pot.w);
    reinterpret_cast<float4*>(out)[v] = o;
}

extern "C" void kernel_launch(void* const* d_in, const int* in_sizes, int n_in,
                              void* d_out, int out_size)
{
    // metadata order:
    // 0: external_input  float[N]
    // 1: weights         float[N*K]
    // 2: connections     int  [N*K]
    // 3: inhibitory_mask float[N]
    // 4: noise           float[STEPS*N]
    // 5: potentials0     float[N]
    // 6: thresholds0     float[N]
    // 7: steps           int  [1]  (compile-time = 10)
    (void)in_sizes; (void)n_in; (void)out_size;
    const float* ext     = (const float*)d_in[0];
    const float* weights = (const float*)d_in[1];
    const int*   conn    = (const int*)  d_in[2];
    const float* inhib   = (const float*)d_in[3];
    const float* noise   = (const float*)d_in[4];
    const float* pot0    = (const float*)d_in[5];
    const float* th0     = (const float*)d_in[6];
    float* out = (float*)d_out;

    const int threads = 256;
    const int blocks  = (NV4 + threads - 1) / threads;

    for (int t = 0; t < N_STEPS; t++) {
        int cur  = t & 1;          // step t scatters into buffer t%2
        int prev = (t - 1) & 1;    // and applies buffer (t-1)%2 (unused at t==0)
        step_kernel<<<blocks, threads>>>(
            noise + (size_t)t * N_NEURONS, ext, pot0, th0, inhib,
            weights, conn, prev, cur, t == 0 ? 1 : 0);
    }
    // apply step 9's scatter (buffer 1) and write output
    final_kernel<<<blocks, threads>>>(inhib, out, (N_STEPS - 1) & 1);
}

// round 5
// speedup vs baseline: 2.5818x; 2.5818x over previous
#include <cuda_runtime.h>
#include <cstdint>

// Problem constants (match reference_code)
#define N_NEURONS 100000
#define AVG_CONN  500
#define N_STEPS   10
#define DECAY     0.95f
#define NV4       (N_NEURONS / 4)            // 25000
#define THREADS   256
#define BLOCKS    ((NV4 + THREADS - 1) / THREADS)   // 98 blocks < 148 SMs -> single wave

// Persistent scratch in device globals (no allocation allowed).
// Zero-initialized at load; all paths restore zeros before exit, so graph
// replays are idempotent.
__device__ __align__(16) float g_post[2][N_NEURONS];
__device__ int          g_any_fired;
__device__ int          g_bar_count;
__device__ unsigned int g_bar_gen;

// Software grid barrier (sense-reversal on a monotonic generation counter).
// Safe because the grid is a single resident wave (98 blocks on 148+ SMs).
__device__ __forceinline__ void grid_barrier()
{
    __syncthreads();
    if (threadIdx.x == 0) {
        __threadfence();                                   // publish prior writes
        unsigned int gen = *(volatile unsigned int*)&g_bar_gen;  // read sense BEFORE arriving
        int ticket = atomicAdd(&g_bar_count, 1);
        if (ticket == BLOCKS - 1) {
            g_bar_count = 0;
            __threadfence();
            atomicAdd(&g_bar_gen, 1u);                     // release
        } else {
            while (*(volatile unsigned int*)&g_bar_gen == gen) {
                __nanosleep(64);                           // back off polling pressure
            }
        }
        __threadfence();                                   // acquire
    }
    __syncthreads();
}

// Scatter one fired neuron's 500 outgoing edges (cold path only).
__device__ __forceinline__ void scatter_edges(int i,
                                              const float* __restrict__ weights,
                                              const int*   __restrict__ conn,
                                              float* __restrict__ pb)
{
    const float4* w4 = reinterpret_cast<const float4*>(weights + (size_t)i * AVG_CONN);
    const int4*   c4 = reinterpret_cast<const int4*>(conn + (size_t)i * AVG_CONN);
    #pragma unroll 4
    for (int k = 0; k < AVG_CONN / 4; k++) {
        float4 w = w4[k];
        int4   c = c4[k];
        atomicAdd(&pb[c.x], w.x);
        atomicAdd(&pb[c.y], w.y);
        atomicAdd(&pb[c.z], w.z);
        atomicAdd(&pb[c.w], w.w);
    }
}

__global__ void __launch_bounds__(THREADS)
brain_kernel(const float* __restrict__ ext,
             const float* __restrict__ weights,
             const int*   __restrict__ conn,
             const float* __restrict__ inhib,
             const float* __restrict__ noise,
             const float* __restrict__ pot0,
             const float* __restrict__ th0,
             float* __restrict__ out)
{
    const int v = blockIdx.x * blockDim.x + threadIdx.x;
    const bool active = (v < NV4);

    const float4* noise4 = reinterpret_cast<const float4*>(noise);

    // ================= Phase 1: speculative, register-resident =================
    // Valid trajectory iff no neuron fires at any step (then post == 0 always).
    // Firing detection is exact: up to the first firing anywhere, speculation
    // equals the true trajectory, so "did anyone fire" is decided correctly.
    float4 pot = make_float4(0.f, 0.f, 0.f, 0.f);
    float4 th  = make_float4(0.f, 0.f, 0.f, 0.f);
    bool any_local = false;

    if (active) {
        pot = reinterpret_cast<const float4*>(pot0)[v];
        th  = reinterpret_cast<const float4*>(th0)[v];
        float4 ex = reinterpret_cast<const float4*>(ext)[v];

        #pragma unroll
        for (int t = 0; t < N_STEPS; t++) {
            float4 nz = noise4[t * NV4 + v];
            pot.x = pot.x * DECAY + nz.x;
            pot.y = pot.y * DECAY + nz.y;
            pot.z = pot.z * DECAY + nz.z;
            pot.w = pot.w * DECAY + nz.w;
            if (t == 0) { pot.x += ex.x; pot.y += ex.y; pot.z += ex.z; pot.w += ex.w; }

            bool f0 = pot.x >= th.x, f1 = pot.y >= th.y;
            bool f2 = pot.z >= th.z, f3 = pot.w >= th.w;
            any_local |= (f0 | f1 | f2 | f3);

            th.x = fminf(fmaxf(th.x + (f0 ? 0.4f : -0.1f), 1.0f), 100.0f);
            th.y = fminf(fmaxf(th.y + (f1 ? 0.4f : -0.1f), 1.0f), 100.0f);
            th.z = fminf(fmaxf(th.z + (f2 ? 0.4f : -0.1f), 1.0f), 100.0f);
            th.w = fminf(fmaxf(th.w + (f3 ? 0.4f : -0.1f), 1.0f), 100.0f);
        }
        if (any_local) g_any_fired = 1;   // racing same-value stores: fine
    }

    grid_barrier();                        // publish the flag grid-wide

    if (g_any_fired == 0) {
        // Fast path: no firing anywhere -> post always zero -> output = pot.
        if (active) reinterpret_cast<float4*>(out)[v] = pot;
        return;                            // uniform branch across the grid
    }

    // ================= Phase 2: exact replay with scatter (cold) =================
    float4 sg = make_float4(0.f, 0.f, 0.f, 0.f);
    if (active) {
        pot = reinterpret_cast<const float4*>(pot0)[v];
        th  = reinterpret_cast<const float4*>(th0)[v];
        float4 ih = reinterpret_cast<const float4*>(inhib)[v];
        sg.x = 1.0f - 2.0f * ih.x;
        sg.y = 1.0f - 2.0f * ih.y;
        sg.z = 1.0f - 2.0f * ih.z;
        sg.w = 1.0f - 2.0f * ih.w;
    }

    for (int t = 0; t < N_STEPS; t++) {
        if (active) {
            // apply previous step's scatter (buffer (t-1)&1), then decay+noise
            if (t > 0) {
                float4* pprev = reinterpret_cast<float4*>(g_post[(t - 1) & 1]);
                float4 p = pprev[v];
                pprev[v] = make_float4(0.f, 0.f, 0.f, 0.f);
                pot.x = fmaf(sg.x, p.x, pot.x);
                pot.y = fmaf(sg.y, p.y, pot.y);
                pot.z = fmaf(sg.z, p.z, pot.z);
                pot.w = fmaf(sg.w, p.w, pot.w);
            }
            float4 nz = noise4[t * NV4 + v];
            pot.x = pot.x * DECAY + nz.x;
            pot.y = pot.y * DECAY + nz.y;
            pot.z = pot.z * DECAY + nz.z;
            pot.w = pot.w * DECAY + nz.w;
            if (t == 0) {
                float4 ex = reinterpret_cast<const float4*>(ext)[v];
                pot.x += ex.x; pot.y += ex.y; pot.z += ex.z; pot.w += ex.w;
            }

            bool f0 = pot.x >= th.x, f1 = pot.y >= th.y;
            bool f2 = pot.z >= th.z, f3 = pot.w >= th.w;

            th.x = fminf(fmaxf(th.x + (f0 ? 0.4f : -0.1f), 1.0f), 100.0f);
            th.y = fminf(fmaxf(th.y + (f1 ? 0.4f : -0.1f), 1.0f), 100.0f);
            th.z = fminf(fmaxf(th.z + (f2 ? 0.4f : -0.1f), 1.0f), 100.0f);
            th.w = fminf(fmaxf(th.w + (f3 ? 0.4f : -0.1f), 1.0f), 100.0f);

            if (f0 | f1 | f2 | f3) {
                float* pb = g_post[t & 1];
                int i0 = v * 4;
                if (f0) scatter_edges(i0 + 0, weights, conn, pb);
                if (f1) scatter_edges(i0 + 1, weights, conn, pb);
                if (f2) scatter_edges(i0 + 2, weights, conn, pb);
                if (f3) scatter_edges(i0 + 3, weights, conn, pb);
            }
        }
        grid_barrier();   // scatter of step t visible before apply at step t+1
    }

    if (active) {
        // apply step 9's scatter (buffer 1) and write output; restore zeros
        float4* plast = reinterpret_cast<float4*>(g_post[(N_STEPS - 1) & 1]);
        float4 p = plast[v];
        plast[v] = make_float4(0.f, 0.f, 0.f, 0.f);
        float4 o;
        o.x = fmaf(sg.x, p.x, pot.x);
        o.y = fmaf(sg.y, p.y, pot.y);
        o.z = fmaf(sg.z, p.z, pot.z);
        o.w = fmaf(sg.w, p.w, pot.w);
        reinterpret_cast<float4*>(out)[v] = o;
    }
    if (v == 0) g_any_fired = 0;   // clean state for next replay (deterministic)
}

extern "C" void kernel_launch(void* const* d_in, const int* in_sizes, int n_in,
                              void* d_out, int out_size)
{
    // metadata order:
    // 0: external_input  float[N]
    // 1: weights         float[N*K]
    // 2: connections     int  [N*K]
    // 3: inhibitory_mask float[N]
    // 4: noise           float[STEPS*N]
    // 5: potentials0     float[N]
    // 6: thresholds0     float[N]
    // 7: steps           int  [1]  (compile-time = 10)
    (void)in_sizes; (void)n_in; (void)out_size;
    const float* ext     = (const float*)d_in[0];
    const float* weights = (const float*)d_in[1];
    const int*   conn    = (const int*)  d_in[2];
    const float* inhib   = (const float*)d_in[3];
    const float* noise   = (const float*)d_in[4];
    const float* pot0    = (const float*)d_in[5];
    const float* th0     = (const float*)d_in[6];
    float* out = (float*)d_out;

    brain_kernel<<<BLOCKS, THREADS>>>(ext, weights, conn, inhib, noise,
                                      pot0, th0, out);
}